// round 6
// baseline (speedup 1.0000x reference)
#include <cuda_runtime.h>
#include <cuda_fp16.h>
#include <cstdint>

#define BB 4
#define NN 16384
#define KK 16
#define CC 64
#define ROWS (BB * NN)          // 65536
#define GROUPS8P (ROWS / 8)     // proj: groups of 8 rows = 8192
#define GROUPS8 (ROWS / 8)      // fused attn: groups of 8 points
#define TOTAL ((size_t)ROWS * CC)

// ---------------- scratch (static device globals) ---------------------------
__device__ __half2 g_kv[TOTAL];   // (ek, v) packed per (row, channel) — 16 MB
__device__ __half  g_h [TOTAL];   // pre-BN FFN output — 8 MB
__device__ float   g_sum [CC];    // BN stats accumulators
__device__ float   g_sum2[CC];

// ============================================================================
// Kernel 1: fused k/v projection (rewritten).
// Thread = (kq = tid>>6 : 16-slice of K dim, c = tid&63 : out channel);
// 16 weights/matrix in registers. x-slices read DIRECTLY from global with
// uniform warp addresses (lanes share kq -> one broadcast request per LDG.128;
// no smem staging, no staging barrier). 8 rows per round; partial sums go
// through a ping-pong smem buffer so each round needs exactly ONE barrier.
// k -> ek = exp(-k/8); (ek, v) packed as half2. Block 0 zeroes BN stats.
// ============================================================================
__global__ void __launch_bounds__(256, 3) proj_kernel(
    const float* __restrict__ feat,
    const float* __restrict__ kw, const float* __restrict__ kb,
    const float* __restrict__ vw, const float* __restrict__ vb)
{
    // [buf][matrix(0=K,1=V)][(row*4+kq)*64 + c] ; 2 * 2 * 2048 floats = 32 KB
    __shared__ float ps[2][2][8 * 4 * 64];

    const int tid = threadIdx.x;
    const int kq  = tid >> 6;
    const int c   = tid & 63;

    if (blockIdx.x == 0 && tid < CC) { g_sum[tid] = 0.f; g_sum2[tid] = 0.f; }

    float wk[16], wv[16];
#pragma unroll
    for (int i = 0; i < 16; i++) {
        wk[i] = kw[(kq * 16 + i) * CC + c];
        wv[i] = vw[(kq * 16 + i) * CC + c];
    }
    const float kbias = kb[c];
    const float vbias = vb[c];

    const int r0 = tid >> 6;        // reduce phase: rows r0 and r0+4

    int buf = 0;
    for (int g = blockIdx.x; g < GROUPS8P; g += gridDim.x) {
        const size_t base = (size_t)g * (8 * CC);

        // ---- compute phase: 8 rows, partials to smem (no pre-barrier) ------
#pragma unroll
        for (int r = 0; r < 8; r++) {
            const float4* x4 = (const float4*)(feat + base + r * CC + kq * 16);
            float pk = 0.f, pv = 0.f;
#pragma unroll
            for (int i4 = 0; i4 < 4; i4++) {
                float4 xv = x4[i4];
                pk = fmaf(xv.x, wk[i4 * 4 + 0], pk); pv = fmaf(xv.x, wv[i4 * 4 + 0], pv);
                pk = fmaf(xv.y, wk[i4 * 4 + 1], pk); pv = fmaf(xv.y, wv[i4 * 4 + 1], pv);
                pk = fmaf(xv.z, wk[i4 * 4 + 2], pk); pv = fmaf(xv.z, wv[i4 * 4 + 2], pv);
                pk = fmaf(xv.w, wk[i4 * 4 + 3], pk); pv = fmaf(xv.w, wv[i4 * 4 + 3], pv);
            }
            ps[buf][0][(r * 4 + kq) * 64 + c] = pk;
            ps[buf][1][(r * 4 + kq) * 64 + c] = pv;
        }
        __syncthreads();   // the ONLY barrier per group (ping-pong buffers)

        // ---- reduce phase: each thread finalizes rows r0 and r0+4 ----------
#pragma unroll
        for (int rr = 0; rr < 2; rr++) {
            const int r = r0 + rr * 4;
            float sk = ps[buf][0][(r * 4 + 0) * 64 + c] + ps[buf][0][(r * 4 + 1) * 64 + c]
                     + ps[buf][0][(r * 4 + 2) * 64 + c] + ps[buf][0][(r * 4 + 3) * 64 + c] + kbias;
            float sv = ps[buf][1][(r * 4 + 0) * 64 + c] + ps[buf][1][(r * 4 + 1) * 64 + c]
                     + ps[buf][1][(r * 4 + 2) * 64 + c] + ps[buf][1][(r * 4 + 3) * 64 + c] + vbias;
            float ek = __expf(-sk * 0.125f);   // exp(-k/8): q cancels in softmax
            g_kv[base + r * CC + c] = __floats2half2_rn(ek, sv);
        }
        buf ^= 1;
    }
}

// ============================================================================
// Kernel 2: fused local attention + FFN GEMV + BN stat accumulation.
// (unchanged from the passing Round-4 kernel)
// ============================================================================
__global__ void __launch_bounds__(256, 2) attn_ffn_kernel(
    const void* __restrict__ idx_raw,
    const float* __restrict__ fw, const float* __restrict__ fb)
{
    __shared__ float xs[8 * 64];     // ctx rows for 8 points
    __shared__ float ps[32 * 64];    // GEMV partials; reused for stat reduce

    const int tid  = threadIdx.x;
    const int lane = tid & 31;
    const int w    = tid >> 5;       // warp = which point in the group
    const int kq   = tid >> 6;       // GEMV: K-slice
    const int c    = tid & 63;       // GEMV: out channel

    const unsigned* pw = (const unsigned*)idx_raw;
    const bool is64 = ((pw[1] | pw[3] | pw[5] | pw[7]) == 0u);

    float fwreg[16];
#pragma unroll
    for (int i = 0; i < 16; i++) fwreg[i] = fw[(kq * 16 + i) * CC + c];
    const float fbias = fb[c];

    float acc_s = 0.f, acc_s2 = 0.f;

    for (int g = blockIdx.x; g < GROUPS8; g += gridDim.x) {
        // ---- attention: one warp per point, lane owns channels 2l, 2l+1 ----
        const int p = g * 8 + w;
        const int b = p >> 14;                 // N = 16384
        int nb = 0;
        if (lane < KK) {
            long long iv = is64 ? ((const long long*)idx_raw)[(size_t)p * KK + lane]
                                : (long long)((const int*)idx_raw)[(size_t)p * KK + lane];
            nb = b * NN + (int)iv;
        }

        float ex[KK], ey[KK], vx[KK], vy[KK];
        float sx = 0.f, sy = 0.f;
#pragma unroll
        for (int j = 0; j < KK; j++) {
            int off = __shfl_sync(0xffffffffu, nb, j);
            uint2 r = ((const uint2*)(g_kv + (size_t)off * CC))[lane];
            float2 f0 = __half22float2(*(__half2*)&r.x);
            float2 f1 = __half22float2(*(__half2*)&r.y);
            ex[j] = f0.x; vx[j] = f0.y;
            ey[j] = f1.x; vy[j] = f1.y;
            sx += f0.x;   sy += f1.x;
        }
        const float ix = __fdividef(1.f, sx);
        const float iy = __fdividef(1.f, sy);

        float mx = -3.402823466e38f, my = -3.402823466e38f;
#pragma unroll
        for (int j = 0; j < KK; j++) {
            mx = fmaxf(mx, fmaf(ex[j], ix, -1.f) * vx[j]);   // (softmax-1) * v
            my = fmaxf(my, fmaf(ey[j], iy, -1.f) * vy[j]);
        }
        ((float2*)(xs + w * 64))[lane] = make_float2(mx, my);
        __syncthreads();

        // ---- FFN GEMV on the 8 ctx rows (x broadcast from smem) ------------
#pragma unroll
        for (int row = 0; row < 8; row++) {
            float pacc = 0.f;
            const float4* x4 = (const float4*)(xs + row * 64 + kq * 16);
#pragma unroll
            for (int i4 = 0; i4 < 4; i4++) {
                float4 xv = x4[i4];
                pacc = fmaf(xv.x, fwreg[i4 * 4 + 0], pacc);
                pacc = fmaf(xv.y, fwreg[i4 * 4 + 1], pacc);
                pacc = fmaf(xv.z, fwreg[i4 * 4 + 2], pacc);
                pacc = fmaf(xv.w, fwreg[i4 * 4 + 3], pacc);
            }
            ps[(row * 4 + kq) * 64 + c] = pacc;
        }
        __syncthreads();

        // ---- reduce partials, store h (fp16), accumulate stats -------------
#pragma unroll
        for (int rpass = 0; rpass < 2; rpass++) {
            const int row = (tid >> 6) + rpass * 4;
            float h = ps[(row * 4 + 0) * 64 + c] + ps[(row * 4 + 1) * 64 + c]
                    + ps[(row * 4 + 2) * 64 + c] + ps[(row * 4 + 3) * 64 + c] + fbias;
            g_h[(size_t)(g * 8 + row) * CC + c] = __float2half_rn(h);
            acc_s  += h;
            acc_s2 += h * h;
        }
        __syncthreads();
    }

    // ---- block-level stat reduction -> global atomics ----------------------
    ps[tid] = acc_s;  __syncthreads();
    if (tid < CC)
        atomicAdd(&g_sum[tid],  ps[tid] + ps[tid + 64] + ps[tid + 128] + ps[tid + 192]);
    __syncthreads();
    ps[tid] = acc_s2; __syncthreads();
    if (tid < CC)
        atomicAdd(&g_sum2[tid], ps[tid] + ps[tid + 64] + ps[tid + 128] + ps[tid + 192]);
}

// ============================================================================
// Kernel 3: finalize. BN scale/shift from stats, then BN + LeakyReLU +
// residual. (unchanged from Round 4)
// ============================================================================
__global__ void __launch_bounds__(256) final_kernel(
    const float* __restrict__ feat,
    const float* __restrict__ gamma, const float* __restrict__ beta,
    float* __restrict__ out)
{
    __shared__ float s_scale[CC], s_shift[CC];
    if (threadIdx.x < CC) {
        const int  cc   = threadIdx.x;
        const float inv = 1.f / (float)ROWS;
        float m    = g_sum[cc] * inv;
        float var  = g_sum2[cc] * inv - m * m;
        float rstd = rsqrtf(var + 1e-5f);
        float sc   = rstd * gamma[cc];
        s_scale[cc] = sc;
        s_shift[cc] = beta[cc] - m * sc;
    }
    __syncthreads();

    const size_t total4 = TOTAL / 4;                 // groups of 4 channels
    const uint2*  h2 = (const uint2*)g_h;            // 4 halves per uint2
    const float4* f4 = (const float4*)feat;
    float4*       o4 = (float4*)out;
    const size_t stride = (size_t)gridDim.x * blockDim.x * 2;

    for (size_t i = ((size_t)blockIdx.x * blockDim.x + threadIdx.x) * 2;
         i + 1 < total4; i += stride) {
#pragma unroll
        for (int u = 0; u < 2; u++) {
            const size_t ii = i + u;
            const int c0 = (int)(ii & 15) * 4;
            uint2 hr = h2[ii];
            float4 f = f4[ii];
            float2 ha = __half22float2(*(__half2*)&hr.x);
            float2 hb = __half22float2(*(__half2*)&hr.y);
            float r0 = ha.x * s_scale[c0 + 0] + s_shift[c0 + 0];
            float r1 = ha.y * s_scale[c0 + 1] + s_shift[c0 + 1];
            float r2 = hb.x * s_scale[c0 + 2] + s_shift[c0 + 2];
            float r3 = hb.y * s_scale[c0 + 3] + s_shift[c0 + 3];
            r0 = (r0 >= 0.f) ? r0 : 0.2f * r0;
            r1 = (r1 >= 0.f) ? r1 : 0.2f * r1;
            r2 = (r2 >= 0.f) ? r2 : 0.2f * r2;
            r3 = (r3 >= 0.f) ? r3 : 0.2f * r3;
            o4[ii] = make_float4(f.x + r0, f.y + r1, f.z + r2, f.w + r3);
        }
    }
}

// ============================================================================
// launch: features(0) pos(1) qw(2) qb(3) kw(4) kb(5) vw(6) vb(7)
//         fw(8) fb(9) gamma(10) beta(11) idx(12)
// pos / qw / qb are mathematically unused (q cancels inside softmax).
// ============================================================================
extern "C" void kernel_launch(void* const* d_in, const int* in_sizes, int n_in,
                              void* d_out, int out_size)
{
    const float* feat  = (const float*)d_in[0];
    const float* kw    = (const float*)d_in[4];
    const float* kb    = (const float*)d_in[5];
    const float* vw    = (const float*)d_in[6];
    const float* vb    = (const float*)d_in[7];
    const float* fw    = (const float*)d_in[8];
    const float* fb    = (const float*)d_in[9];
    const float* gamma = (const float*)d_in[10];
    const float* beta  = (const float*)d_in[11];
    const void*  idx   = (const void*)d_in[12];
    float* out = (float*)d_out;

    proj_kernel     <<<1184, 256>>>(feat, kw, kb, vw, vb);
    attn_ffn_kernel <<<1184, 256>>>(idx, fw, fb);
    final_kernel    <<<1024, 256>>>(feat, gamma, beta, out);
}

// round 7
// speedup vs baseline: 1.1003x; 1.1003x over previous
#include <cuda_runtime.h>
#include <cuda_fp16.h>
#include <cstdint>

#define BB 4
#define NN 16384
#define KK 16
#define CC 64
#define ROWS (BB * NN)          // 65536
#define GROUPS8P (ROWS / 8)     // proj: groups of 8 rows = 8192
#define GROUPS8 (ROWS / 8)      // fused attn: groups of 8 points
#define TOTAL ((size_t)ROWS * CC)

// ---------------- scratch (static device globals) ---------------------------
__device__ __half2 g_kv[TOTAL];   // (ek, v) packed per (row, channel) — 16 MB
__device__ __half  g_h [TOTAL];   // pre-BN FFN output — 8 MB
__device__ float   g_sum [CC];    // BN stats accumulators
__device__ float   g_sum2[CC];

// ---------------- packed fp32x2 helpers (Blackwell FFMA2) --------------------
__device__ __forceinline__ unsigned long long pk2(float lo, float hi) {
    unsigned long long r;
    asm("mov.b64 %0, {%1, %2};" : "=l"(r) : "f"(lo), "f"(hi));
    return r;
}
__device__ __forceinline__ unsigned long long ffma2(
    unsigned long long a, unsigned long long b, unsigned long long c) {
    unsigned long long d;
    asm("fma.rn.f32x2 %0, %1, %2, %3;" : "=l"(d) : "l"(a), "l"(b), "l"(c));
    return d;
}
__device__ __forceinline__ float hsum2(unsigned long long a) {
    float lo, hi;
    asm("mov.b64 {%0, %1}, %2;" : "=f"(lo), "=f"(hi) : "l"(a));
    return lo + hi;
}

// ============================================================================
// Kernel 1: fused k/v projection, v3.
// R4's cooperative staging (read feat ONCE per block via coalesced loads;
// LDS broadcast to warps) + 8-row groups + ping-pong xs AND ps buffers so
// each group costs exactly ONE __syncthreads + packed f32x2 FMAs along K
// (2 MACs/inst) + software-pipelined prefetch of the next group's rows.
// Thread = (kq = tid>>6 : 16-slice of K, c = tid&63). k -> ek = exp(-k/8);
// (ek, v) packed as half2. Block 0 zeroes the BN accumulators.
// ============================================================================
__global__ void __launch_bounds__(256, 3) proj_kernel(
    const float* __restrict__ feat,
    const float* __restrict__ kw, const float* __restrict__ kb,
    const float* __restrict__ vw, const float* __restrict__ vb)
{
    __shared__ float xs[2][8 * 64];          // staged rows, ping-pong (4 KB)
    __shared__ float ps[2][2][8 * 4 * 64];   // partials [buf][mat], ping-pong (32 KB)

    const int tid = threadIdx.x;
    const int kq  = tid >> 6;
    const int c   = tid & 63;

    if (blockIdx.x == 0 && tid < CC) { g_sum[tid] = 0.f; g_sum2[tid] = 0.f; }

    // weights packed as (w_{2i}, w_{2i+1}) pairs along K
    unsigned long long wk2[8], wv2[8];
#pragma unroll
    for (int i = 0; i < 8; i++) {
        wk2[i] = pk2(kw[(kq * 16 + 2 * i) * CC + c], kw[(kq * 16 + 2 * i + 1) * CC + c]);
        wv2[i] = pk2(vw[(kq * 16 + 2 * i) * CC + c], vw[(kq * 16 + 2 * i + 1) * CC + c]);
    }
    const float kbias = kb[c];
    const float vbias = vb[c];
    const int r0 = tid >> 6;                 // reduce phase: rows r0, r0+4

    // prologue: stage first group (8 rows = 256 float2, one per thread)
    int g = blockIdx.x;
    ((float2*)xs[0])[tid] = ((const float2*)feat)[(size_t)g * 256 + tid];
    __syncthreads();

    int buf = 0;
    for (; g < GROUPS8P; g += gridDim.x) {
        const int  gn  = g + gridDim.x;
        const bool has = (gn < GROUPS8P);
        float2 pre;
        if (has) pre = ((const float2*)feat)[(size_t)gn * 256 + tid];  // LDG early

        // ---- compute: 8 rows, packed f32x2 FMAs, partials to ps[buf] -------
#pragma unroll
        for (int r = 0; r < 8; r++) {
            const ulonglong2* x4 = (const ulonglong2*)(xs[buf] + r * 64 + kq * 16);
            unsigned long long ak = 0ULL, av = 0ULL;   // (+0.f, +0.f)
#pragma unroll
            for (int i = 0; i < 4; i++) {
                ulonglong2 q = x4[i];                   // (x2i, x2i+1), (x2i+2, x2i+3)
                ak = ffma2(q.x, wk2[2 * i + 0], ak);
                av = ffma2(q.x, wv2[2 * i + 0], av);
                ak = ffma2(q.y, wk2[2 * i + 1], ak);
                av = ffma2(q.y, wv2[2 * i + 1], av);
            }
            ps[buf][0][(r * 4 + kq) * 64 + c] = hsum2(ak);
            ps[buf][1][(r * 4 + kq) * 64 + c] = hsum2(av);
        }

        if (has) ((float2*)xs[buf ^ 1])[tid] = pre;     // STS after compute (latency hidden)
        __syncthreads();   // the ONLY barrier: C(i)->R(i) and S(i+1)->C(i+1)

        // ---- reduce: each thread finalizes rows r0, r0+4 -------------------
#pragma unroll
        for (int rr = 0; rr < 2; rr++) {
            const int r = r0 + rr * 4;
            float sk = ps[buf][0][(r * 4 + 0) * 64 + c] + ps[buf][0][(r * 4 + 1) * 64 + c]
                     + ps[buf][0][(r * 4 + 2) * 64 + c] + ps[buf][0][(r * 4 + 3) * 64 + c] + kbias;
            float sv = ps[buf][1][(r * 4 + 0) * 64 + c] + ps[buf][1][(r * 4 + 1) * 64 + c]
                     + ps[buf][1][(r * 4 + 2) * 64 + c] + ps[buf][1][(r * 4 + 3) * 64 + c] + vbias;
            float ek = __expf(-sk * 0.125f);            // exp(-k/8): q cancels in softmax
            g_kv[(size_t)g * 512 + r * 64 + c] = __floats2half2_rn(ek, sv);
        }
        buf ^= 1;
    }
}

// ============================================================================
// Kernel 2: fused local attention + FFN GEMV + BN stat accumulation.
// (byte-identical to the 100.7us passing kernel)
// ============================================================================
__global__ void __launch_bounds__(256, 2) attn_ffn_kernel(
    const void* __restrict__ idx_raw,
    const float* __restrict__ fw, const float* __restrict__ fb)
{
    __shared__ float xs[8 * 64];     // ctx rows for 8 points
    __shared__ float ps[32 * 64];    // GEMV partials; reused for stat reduce

    const int tid  = threadIdx.x;
    const int lane = tid & 31;
    const int w    = tid >> 5;       // warp = which point in the group
    const int kq   = tid >> 6;       // GEMV: K-slice
    const int c    = tid & 63;       // GEMV: out channel

    const unsigned* pw = (const unsigned*)idx_raw;
    const bool is64 = ((pw[1] | pw[3] | pw[5] | pw[7]) == 0u);

    float fwreg[16];
#pragma unroll
    for (int i = 0; i < 16; i++) fwreg[i] = fw[(kq * 16 + i) * CC + c];
    const float fbias = fb[c];

    float acc_s = 0.f, acc_s2 = 0.f;

    for (int g = blockIdx.x; g < GROUPS8; g += gridDim.x) {
        // ---- attention: one warp per point, lane owns channels 2l, 2l+1 ----
        const int p = g * 8 + w;
        const int b = p >> 14;                 // N = 16384
        int nb = 0;
        if (lane < KK) {
            long long iv = is64 ? ((const long long*)idx_raw)[(size_t)p * KK + lane]
                                : (long long)((const int*)idx_raw)[(size_t)p * KK + lane];
            nb = b * NN + (int)iv;
        }

        float ex[KK], ey[KK], vx[KK], vy[KK];
        float sx = 0.f, sy = 0.f;
#pragma unroll
        for (int j = 0; j < KK; j++) {
            int off = __shfl_sync(0xffffffffu, nb, j);
            uint2 r = ((const uint2*)(g_kv + (size_t)off * CC))[lane];
            float2 f0 = __half22float2(*(__half2*)&r.x);
            float2 f1 = __half22float2(*(__half2*)&r.y);
            ex[j] = f0.x; vx[j] = f0.y;
            ey[j] = f1.x; vy[j] = f1.y;
            sx += f0.x;   sy += f1.x;
        }
        const float ix = __fdividef(1.f, sx);
        const float iy = __fdividef(1.f, sy);

        float mx = -3.402823466e38f, my = -3.402823466e38f;
#pragma unroll
        for (int j = 0; j < KK; j++) {
            mx = fmaxf(mx, fmaf(ex[j], ix, -1.f) * vx[j]);   // (softmax-1) * v
            my = fmaxf(my, fmaf(ey[j], iy, -1.f) * vy[j]);
        }
        ((float2*)(xs + w * 64))[lane] = make_float2(mx, my);
        __syncthreads();

        // ---- FFN GEMV on the 8 ctx rows (x broadcast from smem) ------------
#pragma unroll
        for (int row = 0; row < 8; row++) {
            float pacc = 0.f;
            const float4* x4 = (const float4*)(xs + row * 64 + kq * 16);
#pragma unroll
            for (int i4 = 0; i4 < 4; i4++) {
                float4 xv = x4[i4];
                pacc = fmaf(xv.x, fwreg[i4 * 4 + 0], pacc);
                pacc = fmaf(xv.y, fwreg[i4 * 4 + 1], pacc);
                pacc = fmaf(xv.z, fwreg[i4 * 4 + 2], pacc);
                pacc = fmaf(xv.w, fwreg[i4 * 4 + 3], pacc);
            }
            ps[(row * 4 + kq) * 64 + c] = pacc;
        }
        __syncthreads();

        // ---- reduce partials, store h (fp16), accumulate stats -------------
#pragma unroll
        for (int rpass = 0; rpass < 2; rpass++) {
            const int row = (tid >> 6) + rpass * 4;
            float h = ps[(row * 4 + 0) * 64 + c] + ps[(row * 4 + 1) * 64 + c]
                    + ps[(row * 4 + 2) * 64 + c] + ps[(row * 4 + 3) * 64 + c] + fbias;
            g_h[(size_t)(g * 8 + row) * CC + c] = __float2half_rn(h);
            acc_s  += h;
            acc_s2 += h * h;
        }
        __syncthreads();
    }

    // ---- block-level stat reduction -> global atomics ----------------------
    ps[tid] = acc_s;  __syncthreads();
    if (tid < CC)
        atomicAdd(&g_sum[tid],  ps[tid] + ps[tid + 64] + ps[tid + 128] + ps[tid + 192]);
    __syncthreads();
    ps[tid] = acc_s2; __syncthreads();
    if (tid < CC)
        atomicAdd(&g_sum2[tid], ps[tid] + ps[tid + 64] + ps[tid + 128] + ps[tid + 192]);
}

// ============================================================================
// Kernel 3: finalize. BN scale/shift from stats, then BN + LeakyReLU +
// residual. (byte-identical to the passing kernel)
// ============================================================================
__global__ void __launch_bounds__(256) final_kernel(
    const float* __restrict__ feat,
    const float* __restrict__ gamma, const float* __restrict__ beta,
    float* __restrict__ out)
{
    __shared__ float s_scale[CC], s_shift[CC];
    if (threadIdx.x < CC) {
        const int  cc   = threadIdx.x;
        const float inv = 1.f / (float)ROWS;
        float m    = g_sum[cc] * inv;
        float var  = g_sum2[cc] * inv - m * m;
        float rstd = rsqrtf(var + 1e-5f);
        float sc   = rstd * gamma[cc];
        s_scale[cc] = sc;
        s_shift[cc] = beta[cc] - m * sc;
    }
    __syncthreads();

    const size_t total4 = TOTAL / 4;                 // groups of 4 channels
    const uint2*  h2 = (const uint2*)g_h;            // 4 halves per uint2
    const float4* f4 = (const float4*)feat;
    float4*       o4 = (float4*)out;
    const size_t stride = (size_t)gridDim.x * blockDim.x * 2;

    for (size_t i = ((size_t)blockIdx.x * blockDim.x + threadIdx.x) * 2;
         i + 1 < total4; i += stride) {
#pragma unroll
        for (int u = 0; u < 2; u++) {
            const size_t ii = i + u;
            const int c0 = (int)(ii & 15) * 4;
            uint2 hr = h2[ii];
            float4 f = f4[ii];
            float2 ha = __half22float2(*(__half2*)&hr.x);
            float2 hb = __half22float2(*(__half2*)&hr.y);
            float r0 = ha.x * s_scale[c0 + 0] + s_shift[c0 + 0];
            float r1 = ha.y * s_scale[c0 + 1] + s_shift[c0 + 1];
            float r2 = hb.x * s_scale[c0 + 2] + s_shift[c0 + 2];
            float r3 = hb.y * s_scale[c0 + 3] + s_shift[c0 + 3];
            r0 = (r0 >= 0.f) ? r0 : 0.2f * r0;
            r1 = (r1 >= 0.f) ? r1 : 0.2f * r1;
            r2 = (r2 >= 0.f) ? r2 : 0.2f * r2;
            r3 = (r3 >= 0.f) ? r3 : 0.2f * r3;
            o4[ii] = make_float4(f.x + r0, f.y + r1, f.z + r2, f.w + r3);
        }
    }
}

// ============================================================================
// launch: features(0) pos(1) qw(2) qb(3) kw(4) kb(5) vw(6) vb(7)
//         fw(8) fb(9) gamma(10) beta(11) idx(12)
// pos / qw / qb are mathematically unused (q cancels inside softmax).
// ============================================================================
extern "C" void kernel_launch(void* const* d_in, const int* in_sizes, int n_in,
                              void* d_out, int out_size)
{
    const float* feat  = (const float*)d_in[0];
    const float* kw    = (const float*)d_in[4];
    const float* kb    = (const float*)d_in[5];
    const float* vw    = (const float*)d_in[6];
    const float* vb    = (const float*)d_in[7];
    const float* fw    = (const float*)d_in[8];
    const float* fb    = (const float*)d_in[9];
    const float* gamma = (const float*)d_in[10];
    const float* beta  = (const float*)d_in[11];
    const void*  idx   = (const void*)d_in[12];
    float* out = (float*)d_out;

    proj_kernel     <<<444, 256>>>(feat, kw, kb, vw, vb);   // 3 CTAs x 148 SMs
    attn_ffn_kernel <<<1184, 256>>>(idx, fw, fb);
    final_kernel    <<<1024, 256>>>(feat, gamma, beta, out);
}